// round 1
// baseline (speedup 1.0000x reference)
#include <cuda_runtime.h>
#include <math.h>
#include <stdint.h>

// ---------------- problem constants ----------------
#define BATCH    4
#define SEQLEN   2048
#define D_MODEL  1024
#define D_STATE  64
#define D_CONV   4
#define HEADDIM  64
#define D_INNER  2048
#define NHEADS   32
#define CONV_DIM 2176          // D_INNER + 2*D_STATE
#define D_IN_PROJ 4256         // 2*D_INNER + 2*D_STATE + NHEADS
#define NROWS    (BATCH * SEQLEN)   // 8192

// ---------------- scratch (static device globals: no allocs allowed) ----------------
__device__ float g_zxbcdt[(size_t)NROWS * D_IN_PROJ];   // 139.5 MB
__device__ float g_xh[(size_t)NROWS * D_INNER];         // 67 MB (post conv+silu)
__device__ float g_Bm[NROWS * D_STATE];
__device__ float g_Cm[NROWS * D_STATE];
__device__ float g_dt[NROWS * NHEADS];
__device__ float g_yscan[(size_t)NROWS * D_INNER];
__device__ float g_y[(size_t)NROWS * D_INNER];

// ---------------- fp32 SIMT GEMM: C[M,N] = A[M,K] @ B[K,N], all row-major ----------------
// BM=128, BN=64, BK=16, 256 threads, 8x4 per-thread tile.
// Requires M%128==0, K%16==0, N%4==0. N edge handled by guards.
__global__ __launch_bounds__(256)
void gemm_f32(const float* __restrict__ A, const float* __restrict__ Bw,
              float* __restrict__ C, int M, int N, int K) {
    constexpr int BM = 128, BN = 64, BK = 16, TM = 8, TN = 4;
    __shared__ float As[BK][BM];   // transposed: As[k][m]
    __shared__ float Bs[BK][BN];

    const int tid = threadIdx.x;
    const int bm  = blockIdx.y * BM;
    const int bn  = blockIdx.x * BN;
    const int tm  = (tid / 16) * TM;   // 0..120
    const int tn  = (tid % 16) * TN;   // 0..60

    // A load pattern: 128 rows x 16 floats = 512 float4; 2 per thread
    const int a_row = tid >> 1;           // 0..127
    const int a_c4  = (tid & 1) * 2;      // float4 col 0 or 2
    // B load pattern: 16 rows x 16 float4; 1 per thread
    const int b_row = tid >> 4;           // 0..15
    const int b_c4  = tid & 15;           // 0..15

    float acc[TM][TN];
#pragma unroll
    for (int i = 0; i < TM; i++)
#pragma unroll
        for (int j = 0; j < TN; j++) acc[i][j] = 0.f;

    for (int k0 = 0; k0 < K; k0 += BK) {
        // load A tile (transposed into As)
#pragma unroll
        for (int u = 0; u < 2; u++) {
            const float4 v = *(const float4*)&A[(size_t)(bm + a_row) * K + k0 + (a_c4 + u) * 4];
            const int kk = (a_c4 + u) * 4;
            As[kk + 0][a_row] = v.x;
            As[kk + 1][a_row] = v.y;
            As[kk + 2][a_row] = v.z;
            As[kk + 3][a_row] = v.w;
        }
        // load B tile (guard N edge; N%4==0 so a float4 is fully in or out)
        {
            const int col = bn + b_c4 * 4;
            float4 v = make_float4(0.f, 0.f, 0.f, 0.f);
            if (col < N) v = *(const float4*)&Bw[(size_t)(k0 + b_row) * N + col];
            *(float4*)&Bs[b_row][b_c4 * 4] = v;
        }
        __syncthreads();

#pragma unroll
        for (int k = 0; k < BK; k++) {
            const float4 a0 = *(const float4*)&As[k][tm];
            const float4 a1 = *(const float4*)&As[k][tm + 4];
            const float4 b0 = *(const float4*)&Bs[k][tn];
            const float a[TM] = {a0.x, a0.y, a0.z, a0.w, a1.x, a1.y, a1.z, a1.w};
            const float b[TN] = {b0.x, b0.y, b0.z, b0.w};
#pragma unroll
            for (int i = 0; i < TM; i++)
#pragma unroll
                for (int j = 0; j < TN; j++)
                    acc[i][j] = fmaf(a[i], b[j], acc[i][j]);
        }
        __syncthreads();
    }

    // store (vectorized, guard N edge)
#pragma unroll
    for (int i = 0; i < TM; i++) {
        const int row = bm + tm + i;
        const int col = bn + tn;
        if (col < N) {
            float4 v = make_float4(acc[i][0], acc[i][1], acc[i][2], acc[i][3]);
            *(float4*)&C[(size_t)row * N + col] = v;
        }
    }
}

// ---------------- conv1d (width 4, causal, per-channel) + silu, plus dt softplus ----------------
__global__ __launch_bounds__(256)
void conv_dt_kernel(const float* __restrict__ conv_w, const float* __restrict__ conv_b,
                    const float* __restrict__ dt_bias) {
    const int row = blockIdx.x;           // b*SEQLEN + l
    const int b   = row / SEQLEN;
    const int l   = row - b * SEQLEN;

    for (int c = threadIdx.x; c < CONV_DIM; c += 256) {
        const float4 w = *(const float4*)&conv_w[c * 4];
        float acc = conv_b[c];
        const float wv[4] = {w.x, w.y, w.z, w.w};
#pragma unroll
        for (int k = 0; k < 4; k++) {
            const int lk = l - 3 + k;
            if (lk >= 0)
                acc = fmaf(g_zxbcdt[(size_t)(b * SEQLEN + lk) * D_IN_PROJ + D_INNER + c], wv[k], acc);
        }
        const float sv = acc / (1.f + expf(-acc));   // silu
        if (c < D_INNER)
            g_xh[(size_t)row * D_INNER + c] = sv;
        else if (c < D_INNER + D_STATE)
            g_Bm[row * D_STATE + (c - D_INNER)] = sv;
        else
            g_Cm[row * D_STATE + (c - D_INNER - D_STATE)] = sv;
    }
    if (threadIdx.x < NHEADS) {
        const int h = threadIdx.x;
        const float v = g_zxbcdt[(size_t)row * D_IN_PROJ + D_INNER + CONV_DIM + h] + dt_bias[h];
        g_dt[row * NHEADS + h] = (v > 20.f) ? v : log1pf(expf(v));
    }
}

// ---------------- sequential SSM scan ----------------
// One block per (batch, head). 256 threads: thread t owns state row p = t>>2 and
// D_STATE slice [16*(t&3), 16*(t&3)+16). Ping-pong register prefetch of next step's
// B/C/x/dt hides L2 latency under the 48-FMA/step compute.
__global__ __launch_bounds__(256)
void scan_kernel(const float* __restrict__ A_log, float* __restrict__ yscan) {
    const int b  = blockIdx.x >> 5;
    const int h  = blockIdx.x & 31;
    const int t  = threadIdx.x;
    const int p  = t >> 2;
    const int nq = t & 3;
    const float Acoef = -expf(A_log[h]);

    const float* Bp = g_Bm + (size_t)b * SEQLEN * D_STATE + nq * 16;
    const float* Cp = g_Cm + (size_t)b * SEQLEN * D_STATE + nq * 16;
    const float* xp = g_xh + (size_t)b * SEQLEN * D_INNER + h * HEADDIM + p;
    const float* dp = g_dt + (size_t)b * SEQLEN * NHEADS + h;
    float*       yp = yscan + (size_t)b * SEQLEN * D_INNER + h * HEADDIM + p;

    float hs[16];
#pragma unroll
    for (int i = 0; i < 16; i++) hs[i] = 0.f;

    float B0[16], C0[16], B1[16], C1[16];
    float dt0, x0, dt1, x1;

#define LOADSTEP(BUF_B, BUF_C, BUF_DT, BUF_X, S)                               \
    do {                                                                       \
        const float* _bb = Bp + (size_t)(S) * D_STATE;                         \
        const float* _cc = Cp + (size_t)(S) * D_STATE;                         \
        *(float4*)&(BUF_B)[0]  = *(const float4*)(_bb + 0);                    \
        *(float4*)&(BUF_B)[4]  = *(const float4*)(_bb + 4);                    \
        *(float4*)&(BUF_B)[8]  = *(const float4*)(_bb + 8);                    \
        *(float4*)&(BUF_B)[12] = *(const float4*)(_bb + 12);                   \
        *(float4*)&(BUF_C)[0]  = *(const float4*)(_cc + 0);                    \
        *(float4*)&(BUF_C)[4]  = *(const float4*)(_cc + 4);                    \
        *(float4*)&(BUF_C)[8]  = *(const float4*)(_cc + 8);                    \
        *(float4*)&(BUF_C)[12] = *(const float4*)(_cc + 12);                   \
        (BUF_DT) = dp[(size_t)(S) * NHEADS];                                   \
        (BUF_X)  = xp[(size_t)(S) * D_INNER];                                  \
    } while (0)

#define COMPSTEP(BUF_B, BUF_C, BUF_DT, BUF_X, S)                               \
    do {                                                                       \
        const float dA  = expf((BUF_DT) * Acoef);                              \
        const float dtx = (BUF_DT) * (BUF_X);                                  \
        float acc = 0.f;                                                       \
        _Pragma("unroll")                                                      \
        for (int i = 0; i < 16; i++) {                                         \
            hs[i] = fmaf(hs[i], dA, dtx * (BUF_B)[i]);                         \
            acc   = fmaf(hs[i], (BUF_C)[i], acc);                              \
        }                                                                      \
        acc += __shfl_xor_sync(0xffffffffu, acc, 1);                           \
        acc += __shfl_xor_sync(0xffffffffu, acc, 2);                           \
        if (nq == 0) yp[(size_t)(S) * D_INNER] = acc;                          \
    } while (0)

    LOADSTEP(B0, C0, dt0, x0, 0);
    for (int s = 0; s < SEQLEN; s += 2) {
        LOADSTEP(B1, C1, dt1, x1, s + 1);         // s+1 <= 2047 always valid
        COMPSTEP(B0, C0, dt0, x0, s);
        if (s + 2 < SEQLEN) LOADSTEP(B0, C0, dt0, x0, s + 2);
        COMPSTEP(B1, C1, dt1, x1, s + 1);
    }
#undef LOADSTEP
#undef COMPSTEP
}

// ---------------- y = (yscan + xh*D) * silu(z); RMSNorm; * norm_w ----------------
__global__ __launch_bounds__(256)
void gate_norm_kernel(const float* __restrict__ Dv, const float* __restrict__ norm_w) {
    const int row = blockIdx.x;
    const size_t base = (size_t)row * D_INNER;

    float vals[8];
    float ss = 0.f;
#pragma unroll
    for (int i = 0; i < 8; i++) {
        const int c = threadIdx.x + i * 256;
        const float yv = g_yscan[base + c] + g_xh[base + c] * Dv[c >> 6];
        const float z  = g_zxbcdt[(size_t)row * D_IN_PROJ + c];
        const float y  = yv * (z / (1.f + expf(-z)));
        vals[i] = y;
        ss = fmaf(y, y, ss);
    }
#pragma unroll
    for (int o = 16; o > 0; o >>= 1) ss += __shfl_xor_sync(0xffffffffu, ss, o);
    __shared__ float wsum[8];
    if ((threadIdx.x & 31) == 0) wsum[threadIdx.x >> 5] = ss;
    __syncthreads();
    float tot = 0.f;
#pragma unroll
    for (int w = 0; w < 8; w++) tot += wsum[w];
    const float inv = rsqrtf(tot * (1.f / D_INNER) + 1e-5f);
#pragma unroll
    for (int i = 0; i < 8; i++) {
        const int c = threadIdx.x + i * 256;
        g_y[base + c] = vals[i] * inv * norm_w[c];
    }
}

// ---------------- launch ----------------
extern "C" void kernel_launch(void* const* d_in, const int* in_sizes, int n_in,
                              void* d_out, int out_size) {
    (void)in_sizes; (void)n_in; (void)out_size;
    const float* x       = (const float*)d_in[0];
    const float* W_in    = (const float*)d_in[1];
    const float* conv_w  = (const float*)d_in[2];
    const float* conv_b  = (const float*)d_in[3];
    const float* dt_bias = (const float*)d_in[4];
    const float* A_log   = (const float*)d_in[5];
    const float* Dv      = (const float*)d_in[6];
    const float* norm_w  = (const float*)d_in[7];
    const float* W_out   = (const float*)d_in[8];
    float* out = (float*)d_out;

    float *zx = nullptr, *yv = nullptr, *ys = nullptr;
    cudaGetSymbolAddress((void**)&zx, g_zxbcdt);
    cudaGetSymbolAddress((void**)&yv, g_y);
    cudaGetSymbolAddress((void**)&ys, g_yscan);

    // 1) zxbcdt = x @ W_in   [8192 x 4256]
    dim3 g1((D_IN_PROJ + 63) / 64, NROWS / 128);
    gemm_f32<<<g1, 256>>>(x, W_in, zx, NROWS, D_IN_PROJ, D_MODEL);

    // 2) conv + silu + dt softplus
    conv_dt_kernel<<<NROWS, 256>>>(conv_w, conv_b, dt_bias);

    // 3) SSM scan: one block per (batch, head)
    scan_kernel<<<BATCH * NHEADS, 256>>>(A_log, ys);

    // 4) gate + RMSNorm
    gate_norm_kernel<<<NROWS, 256>>>(Dv, norm_w);

    // 5) out = y @ W_out   [8192 x 1024]
    dim3 g2(D_MODEL / 64, NROWS / 128);
    gemm_f32<<<g2, 256>>>(yv, W_out, out, NROWS, D_MODEL, D_INNER);
}

// round 2
// speedup vs baseline: 1.9193x; 1.9193x over previous
#include <cuda_runtime.h>
#include <math.h>
#include <stdint.h>

// ---------------- problem constants ----------------
#define BATCH    4
#define SEQLEN   2048
#define D_MODEL  1024
#define D_STATE  64
#define D_CONV   4
#define HEADDIM  64
#define D_INNER  2048
#define NHEADS   32
#define CONV_DIM 2176          // D_INNER + 2*D_STATE
#define D_IN_PROJ 4256         // 2*D_INNER + 2*D_STATE + NHEADS
#define NROWS    (BATCH * SEQLEN)   // 8192

// ---------------- scratch (static device globals: no allocs allowed) ----------------
__device__ float g_zxbcdt[(size_t)NROWS * D_IN_PROJ];   // 139.5 MB
__device__ float g_xh[(size_t)NROWS * D_INNER];         // 67 MB (post conv+silu)
__device__ float g_Bm[NROWS * D_STATE];
__device__ float g_Cm[NROWS * D_STATE];
__device__ float g_dt[NROWS * NHEADS];
__device__ float g_yscan[(size_t)NROWS * D_INNER];
__device__ float g_y[(size_t)NROWS * D_INNER];

// ---------------- tf32 tensor-core GEMM ----------------
// C[M,N] = A[M,K] @ B[K,N], row-major fp32 in/out, tf32 MMA, fp32 accumulate.
// BM=128, BN=64, BK=32, 256 threads (8 warps in 4x2), warp tile 32x32
// = 2 (m16) x 4 (n8) fragments of mma.m16n8k8.
// Requires M%128==0, K%32==0, N%2==0; N edge guarded (zero-fill B, guarded C store).
#define GT_BM 128
#define GT_BN 64
#define GT_BK 32
#define AS_STRIDE 36   // (4m+k)%32 distinct over fragment lanes; STS.128 conflict-free
#define BS_STRIDE 72   // (8k+n)%32 distinct over fragment lanes; STS.128 conflict-free

__device__ __forceinline__ float to_tf32(float x) {
    uint32_t u;
    asm("cvt.rna.tf32.f32 %0, %1;" : "=r"(u) : "f"(x));
    return __uint_as_float(u);
}

__device__ __forceinline__ void mma_tf32(float* d, const uint32_t* a, const uint32_t* b) {
    asm volatile(
        "mma.sync.aligned.m16n8k8.row.col.f32.tf32.tf32.f32 "
        "{%0,%1,%2,%3}, {%4,%5,%6,%7}, {%8,%9}, {%0,%1,%2,%3};\n"
        : "+f"(d[0]), "+f"(d[1]), "+f"(d[2]), "+f"(d[3])
        : "r"(a[0]), "r"(a[1]), "r"(a[2]), "r"(a[3]), "r"(b[0]), "r"(b[1]));
}

__global__ __launch_bounds__(256)
void gemm_tf32(const float* __restrict__ A, const float* __restrict__ Bw,
               float* __restrict__ C, int M, int N, int K) {
    __shared__ float As[GT_BM * AS_STRIDE];   // As[m][k], 18KB
    __shared__ float Bs[GT_BK * BS_STRIDE];   // Bs[k][n], 9KB

    const int tid  = threadIdx.x;
    const int bm   = blockIdx.y * GT_BM;
    const int bn   = blockIdx.x * GT_BN;
    const int warp = tid >> 5;
    const int lane = tid & 31;
    const int wm   = (warp >> 1) * 32;   // warp row offset (0,32,64,96)
    const int wn   = (warp & 1) * 32;    // warp col offset (0,32)
    const int gid  = lane >> 2;          // 0..7
    const int tid4 = lane & 3;           // 0..3

    // global load assignment
    const int arow = tid >> 3;  // 0..31 (+32p), with ak4 covers 128B rows coalesced
    const int ak4  = tid & 7;   // float4 index in k
    const int brow = tid >> 4;  // 0..15 (+16p)
    const int bn4  = tid & 15;  // float4 index in n
    const int bcol = bn + bn4 * 4;
    const bool bvalid = (bcol < N);

    const float* Ab = A + (size_t)bm * K;

    float4 ra[4], rb[2];
    float acc[2][4][4];
#pragma unroll
    for (int mt = 0; mt < 2; mt++)
#pragma unroll
        for (int nt = 0; nt < 4; nt++)
#pragma unroll
            for (int i = 0; i < 4; i++) acc[mt][nt][i] = 0.f;

#define LOAD_TILE(K0)                                                           \
    do {                                                                        \
        _Pragma("unroll")                                                       \
        for (int p = 0; p < 4; p++)                                             \
            ra[p] = *(const float4*)&Ab[(size_t)(arow + 32 * p) * K + (K0) + ak4 * 4]; \
        _Pragma("unroll")                                                       \
        for (int p = 0; p < 2; p++) {                                           \
            float4 v = make_float4(0.f, 0.f, 0.f, 0.f);                         \
            if (bvalid)                                                         \
                v = *(const float4*)&Bw[(size_t)((K0) + brow + 16 * p) * N + bcol]; \
            rb[p] = v;                                                          \
        }                                                                       \
    } while (0)

    const int nit = K / GT_BK;
    LOAD_TILE(0);

    for (int it = 0; it < nit; it++) {
        __syncthreads();   // previous compute done before smem overwrite
        // store tile to smem with tf32 rounding
#pragma unroll
        for (int p = 0; p < 4; p++) {
            float4 v = ra[p];
            v.x = to_tf32(v.x); v.y = to_tf32(v.y);
            v.z = to_tf32(v.z); v.w = to_tf32(v.w);
            *(float4*)&As[(arow + 32 * p) * AS_STRIDE + ak4 * 4] = v;
        }
#pragma unroll
        for (int p = 0; p < 2; p++) {
            float4 v = rb[p];
            v.x = to_tf32(v.x); v.y = to_tf32(v.y);
            v.z = to_tf32(v.z); v.w = to_tf32(v.w);
            *(float4*)&Bs[(brow + 16 * p) * BS_STRIDE + bn4 * 4] = v;
        }
        __syncthreads();

        if (it + 1 < nit) LOAD_TILE((it + 1) * GT_BK);  // overlap with compute

#pragma unroll
        for (int kk = 0; kk < GT_BK; kk += 8) {
            uint32_t af[2][4], bf[4][2];
#pragma unroll
            for (int mt = 0; mt < 2; mt++) {
                const int m0 = wm + mt * 16 + gid;
                af[mt][0] = __float_as_uint(As[(m0)     * AS_STRIDE + kk + tid4]);
                af[mt][1] = __float_as_uint(As[(m0 + 8) * AS_STRIDE + kk + tid4]);
                af[mt][2] = __float_as_uint(As[(m0)     * AS_STRIDE + kk + tid4 + 4]);
                af[mt][3] = __float_as_uint(As[(m0 + 8) * AS_STRIDE + kk + tid4 + 4]);
            }
#pragma unroll
            for (int nt = 0; nt < 4; nt++) {
                const int n0 = wn + nt * 8 + gid;
                bf[nt][0] = __float_as_uint(Bs[(kk + tid4)     * BS_STRIDE + n0]);
                bf[nt][1] = __float_as_uint(Bs[(kk + tid4 + 4) * BS_STRIDE + n0]);
            }
#pragma unroll
            for (int mt = 0; mt < 2; mt++)
#pragma unroll
                for (int nt = 0; nt < 4; nt++)
                    mma_tf32(acc[mt][nt], af[mt], bf[nt]);
        }
    }
#undef LOAD_TILE

    // store C (fp32), pairs (c0,c1)/(c2,c3) are adjacent columns
#pragma unroll
    for (int mt = 0; mt < 2; mt++)
#pragma unroll
        for (int nt = 0; nt < 4; nt++) {
            const int r0 = bm + wm + mt * 16 + gid;
            const int c0 = bn + wn + nt * 8 + 2 * tid4;
            if (c0 < N) {
                *(float2*)&C[(size_t)r0 * N + c0] =
                    make_float2(acc[mt][nt][0], acc[mt][nt][1]);
                *(float2*)&C[(size_t)(r0 + 8) * N + c0] =
                    make_float2(acc[mt][nt][2], acc[mt][nt][3]);
            }
        }
}

// ---------------- conv1d (width 4, causal, per-channel) + silu, plus dt softplus ----------------
__global__ __launch_bounds__(256)
void conv_dt_kernel(const float* __restrict__ conv_w, const float* __restrict__ conv_b,
                    const float* __restrict__ dt_bias) {
    const int row = blockIdx.x;           // b*SEQLEN + l
    const int b   = row / SEQLEN;
    const int l   = row - b * SEQLEN;

    for (int c = threadIdx.x; c < CONV_DIM; c += 256) {
        const float4 w = *(const float4*)&conv_w[c * 4];
        float acc = conv_b[c];
        const float wv[4] = {w.x, w.y, w.z, w.w};
#pragma unroll
        for (int k = 0; k < 4; k++) {
            const int lk = l - 3 + k;
            if (lk >= 0)
                acc = fmaf(g_zxbcdt[(size_t)(b * SEQLEN + lk) * D_IN_PROJ + D_INNER + c], wv[k], acc);
        }
        const float sv = acc / (1.f + expf(-acc));   // silu
        if (c < D_INNER)
            g_xh[(size_t)row * D_INNER + c] = sv;
        else if (c < D_INNER + D_STATE)
            g_Bm[row * D_STATE + (c - D_INNER)] = sv;
        else
            g_Cm[row * D_STATE + (c - D_INNER - D_STATE)] = sv;
    }
    if (threadIdx.x < NHEADS) {
        const int h = threadIdx.x;
        const float v = g_zxbcdt[(size_t)row * D_IN_PROJ + D_INNER + CONV_DIM + h] + dt_bias[h];
        g_dt[row * NHEADS + h] = (v > 20.f) ? v : log1pf(expf(v));
    }
}

// ---------------- sequential SSM scan ----------------
__global__ __launch_bounds__(256)
void scan_kernel(const float* __restrict__ A_log, float* __restrict__ yscan) {
    const int b  = blockIdx.x >> 5;
    const int h  = blockIdx.x & 31;
    const int t  = threadIdx.x;
    const int p  = t >> 2;
    const int nq = t & 3;
    const float Acoef = -expf(A_log[h]);

    const float* Bp = g_Bm + (size_t)b * SEQLEN * D_STATE + nq * 16;
    const float* Cp = g_Cm + (size_t)b * SEQLEN * D_STATE + nq * 16;
    const float* xp = g_xh + (size_t)b * SEQLEN * D_INNER + h * HEADDIM + p;
    const float* dp = g_dt + (size_t)b * SEQLEN * NHEADS + h;
    float*       yp = yscan + (size_t)b * SEQLEN * D_INNER + h * HEADDIM + p;

    float hs[16];
#pragma unroll
    for (int i = 0; i < 16; i++) hs[i] = 0.f;

    float B0[16], C0[16], B1[16], C1[16];
    float dt0, x0, dt1, x1;

#define LOADSTEP(BUF_B, BUF_C, BUF_DT, BUF_X, S)                               \
    do {                                                                       \
        const float* _bb = Bp + (size_t)(S) * D_STATE;                         \
        const float* _cc = Cp + (size_t)(S) * D_STATE;                         \
        *(float4*)&(BUF_B)[0]  = *(const float4*)(_bb + 0);                    \
        *(float4*)&(BUF_B)[4]  = *(const float4*)(_bb + 4);                    \
        *(float4*)&(BUF_B)[8]  = *(const float4*)(_bb + 8);                    \
        *(float4*)&(BUF_B)[12] = *(const float4*)(_bb + 12);                   \
        *(float4*)&(BUF_C)[0]  = *(const float4*)(_cc + 0);                    \
        *(float4*)&(BUF_C)[4]  = *(const float4*)(_cc + 4);                    \
        *(float4*)&(BUF_C)[8]  = *(const float4*)(_cc + 8);                    \
        *(float4*)&(BUF_C)[12] = *(const float4*)(_cc + 12);                   \
        (BUF_DT) = dp[(size_t)(S) * NHEADS];                                   \
        (BUF_X)  = xp[(size_t)(S) * D_INNER];                                  \
    } while (0)

#define COMPSTEP(BUF_B, BUF_C, BUF_DT, BUF_X, S)                               \
    do {                                                                       \
        const float dA  = expf((BUF_DT) * Acoef);                              \
        const float dtx = (BUF_DT) * (BUF_X);                                  \
        float acc = 0.f;                                                       \
        _Pragma("unroll")                                                      \
        for (int i = 0; i < 16; i++) {                                         \
            hs[i] = fmaf(hs[i], dA, dtx * (BUF_B)[i]);                         \
            acc   = fmaf(hs[i], (BUF_C)[i], acc);                              \
        }                                                                      \
        acc += __shfl_xor_sync(0xffffffffu, acc, 1);                           \
        acc += __shfl_xor_sync(0xffffffffu, acc, 2);                           \
        if (nq == 0) yp[(size_t)(S) * D_INNER] = acc;                          \
    } while (0)

    LOADSTEP(B0, C0, dt0, x0, 0);
    for (int s = 0; s < SEQLEN; s += 2) {
        LOADSTEP(B1, C1, dt1, x1, s + 1);
        COMPSTEP(B0, C0, dt0, x0, s);
        if (s + 2 < SEQLEN) LOADSTEP(B0, C0, dt0, x0, s + 2);
        COMPSTEP(B1, C1, dt1, x1, s + 1);
    }
#undef LOADSTEP
#undef COMPSTEP
}

// ---------------- y = (yscan + xh*D) * silu(z); RMSNorm; * norm_w ----------------
__global__ __launch_bounds__(256)
void gate_norm_kernel(const float* __restrict__ Dv, const float* __restrict__ norm_w) {
    const int row = blockIdx.x;
    const size_t base = (size_t)row * D_INNER;

    float vals[8];
    float ss = 0.f;
#pragma unroll
    for (int i = 0; i < 8; i++) {
        const int c = threadIdx.x + i * 256;
        const float yv = g_yscan[base + c] + g_xh[base + c] * Dv[c >> 6];
        const float z  = g_zxbcdt[(size_t)row * D_IN_PROJ + c];
        const float y  = yv * (z / (1.f + expf(-z)));
        vals[i] = y;
        ss = fmaf(y, y, ss);
    }
#pragma unroll
    for (int o = 16; o > 0; o >>= 1) ss += __shfl_xor_sync(0xffffffffu, ss, o);
    __shared__ float wsum[8];
    if ((threadIdx.x & 31) == 0) wsum[threadIdx.x >> 5] = ss;
    __syncthreads();
    float tot = 0.f;
#pragma unroll
    for (int w = 0; w < 8; w++) tot += wsum[w];
    const float inv = rsqrtf(tot * (1.f / D_INNER) + 1e-5f);
#pragma unroll
    for (int i = 0; i < 8; i++) {
        const int c = threadIdx.x + i * 256;
        g_y[base + c] = vals[i] * inv * norm_w[c];
    }
}

// ---------------- launch ----------------
extern "C" void kernel_launch(void* const* d_in, const int* in_sizes, int n_in,
                              void* d_out, int out_size) {
    (void)in_sizes; (void)n_in; (void)out_size;
    const float* x       = (const float*)d_in[0];
    const float* W_in    = (const float*)d_in[1];
    const float* conv_w  = (const float*)d_in[2];
    const float* conv_b  = (const float*)d_in[3];
    const float* dt_bias = (const float*)d_in[4];
    const float* A_log   = (const float*)d_in[5];
    const float* Dv      = (const float*)d_in[6];
    const float* norm_w  = (const float*)d_in[7];
    const float* W_out   = (const float*)d_in[8];
    float* out = (float*)d_out;

    float *zx = nullptr, *yv = nullptr, *ys = nullptr;
    cudaGetSymbolAddress((void**)&zx, g_zxbcdt);
    cudaGetSymbolAddress((void**)&yv, g_y);
    cudaGetSymbolAddress((void**)&ys, g_yscan);

    // 1) zxbcdt = x @ W_in   [8192 x 4256]
    dim3 g1((D_IN_PROJ + GT_BN - 1) / GT_BN, NROWS / GT_BM);
    gemm_tf32<<<g1, 256>>>(x, W_in, zx, NROWS, D_IN_PROJ, D_MODEL);

    // 2) conv + silu + dt softplus
    conv_dt_kernel<<<NROWS, 256>>>(conv_w, conv_b, dt_bias);

    // 3) SSM scan: one block per (batch, head)
    scan_kernel<<<BATCH * NHEADS, 256>>>(A_log, ys);

    // 4) gate + RMSNorm
    gate_norm_kernel<<<NROWS, 256>>>(Dv, norm_w);

    // 5) out = y @ W_out   [8192 x 1024]
    dim3 g2(D_MODEL / GT_BN, NROWS / GT_BM);
    gemm_tf32<<<g2, 256>>>(yv, W_out, out, NROWS, D_MODEL, D_INNER);
}

// round 4
// speedup vs baseline: 2.1659x; 1.1284x over previous
#include <cuda_runtime.h>
#include <math.h>
#include <stdint.h>

// ---------------- problem constants ----------------
#define BATCH    4
#define SEQLEN   2048
#define D_MODEL  1024
#define D_STATE  64
#define D_CONV   4
#define HEADDIM  64
#define D_INNER  2048
#define NHEADS   32
#define CONV_DIM 2176          // D_INNER + 2*D_STATE
#define D_IN_PROJ 4256         // 2*D_INNER + 2*D_STATE + NHEADS
#define NROWS    (BATCH * SEQLEN)   // 8192

// ---------------- scratch (static device globals: no allocs allowed) ----------------
__device__ float g_zxbcdt[(size_t)NROWS * D_IN_PROJ];   // 139.5 MB
__device__ float g_xh[(size_t)NROWS * D_INNER];         // 67 MB (post conv+silu)
__device__ float g_Bm[NROWS * D_STATE];
__device__ float g_Cm[NROWS * D_STATE];
__device__ float g_dt[NROWS * NHEADS];
__device__ float g_yscan[(size_t)NROWS * D_INNER];
__device__ float g_y[(size_t)NROWS * D_INNER];          // gated+normed, tf32-rounded
__device__ float g_xr[(size_t)NROWS * D_MODEL];         // x rounded to tf32
__device__ float g_w1r[(size_t)D_MODEL * D_IN_PROJ];    // W_in rounded
__device__ float g_w2r[(size_t)D_INNER * D_MODEL];      // W_out rounded

// ---------------- helpers ----------------
__device__ __forceinline__ float to_tf32(float x) {
    uint32_t u;
    asm("cvt.rna.tf32.f32 %0, %1;" : "=r"(u) : "f"(x));
    return __uint_as_float(u);
}
__device__ __forceinline__ uint32_t smem_u32(const void* p) {
    uint32_t a;
    asm("{ .reg .u64 t; cvta.to.shared.u64 t, %1; cvt.u32.u64 %0, t; }" : "=r"(a) : "l"(p));
    return a;
}
__device__ __forceinline__ void mma_tf32(float* d, const uint32_t* a, const uint32_t* b) {
    asm volatile(
        "mma.sync.aligned.m16n8k8.row.col.f32.tf32.tf32.f32 "
        "{%0,%1,%2,%3}, {%4,%5,%6,%7}, {%8,%9}, {%0,%1,%2,%3};\n"
        : "+f"(d[0]), "+f"(d[1]), "+f"(d[2]), "+f"(d[3])
        : "r"(a[0]), "r"(a[1]), "r"(a[2]), "r"(a[3]), "r"(b[0]), "r"(b[1]));
}
__device__ __forceinline__ void cp16(uint32_t dst, const float* src) {
    asm volatile("cp.async.cg.shared.global [%0], [%1], 16;" :: "r"(dst), "l"(src));
}
__device__ __forceinline__ void cp16z(uint32_t dst, const float* src, int vsz) {
    asm volatile("cp.async.cg.shared.global [%0], [%1], 16, %2;" :: "r"(dst), "l"(src), "r"(vsz));
}
#define CP_COMMIT() asm volatile("cp.async.commit_group;" ::: "memory")
#define CP_WAIT1()  asm volatile("cp.async.wait_group 1;" ::: "memory")
#define CP_WAIT0()  asm volatile("cp.async.wait_group 0;" ::: "memory")

// round fp32 -> tf32-in-fp32 (vectorized copy)
__global__ __launch_bounds__(256)
void round_tf32_kernel(const float* __restrict__ src, float* __restrict__ dst, size_t n4) {
    const size_t i = (size_t)blockIdx.x * 256 + threadIdx.x;
    if (i < n4) {
        float4 v = ((const float4*)src)[i];
        v.x = to_tf32(v.x); v.y = to_tf32(v.y); v.z = to_tf32(v.z); v.w = to_tf32(v.w);
        ((float4*)dst)[i] = v;
    }
}

// ================= pipelined tf32 GEMM =================
// C[M,N] = A[M,K] @ B[K,N], row-major, operands pre-rounded to tf32.
// CTA 128x128x32, 256 thr (8 warps = 2m x 4n, warp tile 64x32), cp.async
// 2-stage pipeline. M%128==0, K%32==0, N%4==0 (N edge: zero-fill + guarded store).
#define P_AF (128 * 36)          // As floats per stage (stride 36)
#define P_BF (32 * 136)          // Bs floats per stage (stride 136)
#define P_SF (P_AF + P_BF)       // stage floats
#define GEMM_SMEM (P_SF * 2 * 4) // 71680 bytes

__global__ __launch_bounds__(256, 2)
void gemm_tf32_pipe(const float* __restrict__ A, const float* __restrict__ Bw,
                    float* __restrict__ C, int M, int N, int K) {
    extern __shared__ float sm[];
    const uint32_t base = smem_u32(sm);
    const uint32_t sA[2] = { base, base + P_SF * 4 };
    const uint32_t sB[2] = { base + P_AF * 4, base + (P_SF + P_AF) * 4 };

    const int tid  = threadIdx.x;
    const int warp = tid >> 5, lane = tid & 31;
    const int gid  = lane >> 2, tid4 = lane & 3;
    const int bm   = blockIdx.y * 128, bn = blockIdx.x * 128;
    const int wm   = (warp >> 2) * 64;     // 0 or 64
    const int wn   = (warp & 3) * 32;      // 0,32,64,96

    // cp.async mapping: A: (m = tid>>3 + 32p, chunk c = tid&7); B: (k = tid>>5 + 8p, chunk c = tid&31)
    const int am = tid >> 3, ac = tid & 7;
    const int bk = tid >> 5, bc = tid & 31;
    const int bcol = bn + bc * 4;
    const int bvsz = (bcol + 4 <= N) ? 16 : 0;   // 16B chunk all-or-nothing (N%4==0)

    float acc[4][4][4];
#pragma unroll
    for (int mt = 0; mt < 4; mt++)
#pragma unroll
        for (int nt = 0; nt < 4; nt++)
#pragma unroll
            for (int i = 0; i < 4; i++) acc[mt][nt][i] = 0.f;

#define PIPE_LOAD(T)                                                            \
    do {                                                                        \
        const int _buf = (T) & 1; const int _k0 = (T) * 32;                     \
        _Pragma("unroll")                                                       \
        for (int p = 0; p < 4; p++) {                                           \
            const int m = am + 32 * p;                                          \
            cp16(sA[_buf] + (uint32_t)(m * 36 + ac * 4) * 4,                    \
                 A + (size_t)(bm + m) * K + _k0 + ac * 4);                      \
        }                                                                       \
        _Pragma("unroll")                                                       \
        for (int p = 0; p < 4; p++) {                                           \
            const int kk = bk + 8 * p;                                          \
            cp16z(sB[_buf] + (uint32_t)(kk * 136 + bc * 4) * 4,                 \
                  Bw + (size_t)(_k0 + kk) * N + bcol, bvsz);                    \
        }                                                                       \
        CP_COMMIT();                                                            \
    } while (0)

    const int nit = K >> 5;
    PIPE_LOAD(0);

    for (int t = 0; t < nit; t++) {
        if (t + 1 < nit) { PIPE_LOAD(t + 1); CP_WAIT1(); }
        else             { CP_WAIT0(); }
        __syncthreads();

        const float* Asb = sm + ((t & 1) ? P_SF : 0);
        const float* Bsb = Asb + P_AF;
#pragma unroll
        for (int ks = 0; ks < 32; ks += 8) {
            uint32_t af[4][4], bf[4][2];
#pragma unroll
            for (int mt = 0; mt < 4; mt++) {
                const int m0 = wm + mt * 16 + gid;
                af[mt][0] = __float_as_uint(Asb[(m0)     * 36 + ks + tid4]);
                af[mt][1] = __float_as_uint(Asb[(m0 + 8) * 36 + ks + tid4]);
                af[mt][2] = __float_as_uint(Asb[(m0)     * 36 + ks + tid4 + 4]);
                af[mt][3] = __float_as_uint(Asb[(m0 + 8) * 36 + ks + tid4 + 4]);
            }
#pragma unroll
            for (int nt = 0; nt < 4; nt++) {
                const int n0 = wn + nt * 8 + gid;
                bf[nt][0] = __float_as_uint(Bsb[(ks + tid4)     * 136 + n0]);
                bf[nt][1] = __float_as_uint(Bsb[(ks + tid4 + 4) * 136 + n0]);
            }
#pragma unroll
            for (int mt = 0; mt < 4; mt++)
#pragma unroll
                for (int nt = 0; nt < 4; nt++)
                    mma_tf32(acc[mt][nt], af[mt], bf[nt]);
        }
        __syncthreads();   // compute done before this buffer is refilled at t+2
    }
#undef PIPE_LOAD

    // store C
#pragma unroll
    for (int mt = 0; mt < 4; mt++)
#pragma unroll
        for (int nt = 0; nt < 4; nt++) {
            const int r0 = bm + wm + mt * 16 + gid;
            const int c0 = bn + wn + nt * 8 + 2 * tid4;
            if (c0 < N) {
                *(float2*)&C[(size_t)r0 * N + c0] =
                    make_float2(acc[mt][nt][0], acc[mt][nt][1]);
                *(float2*)&C[(size_t)(r0 + 8) * N + c0] =
                    make_float2(acc[mt][nt][2], acc[mt][nt][3]);
            }
        }
}

// ---------------- conv1d + silu, dt softplus ----------------
__global__ __launch_bounds__(256)
void conv_dt_kernel(const float* __restrict__ conv_w, const float* __restrict__ conv_b,
                    const float* __restrict__ dt_bias) {
    const int row = blockIdx.x;
    const int b   = row / SEQLEN;
    const int l   = row - b * SEQLEN;

    for (int c = threadIdx.x; c < CONV_DIM; c += 256) {
        const float4 w = *(const float4*)&conv_w[c * 4];
        float acc = conv_b[c];
        const float wv[4] = {w.x, w.y, w.z, w.w};
#pragma unroll
        for (int k = 0; k < 4; k++) {
            const int lk = l - 3 + k;
            if (lk >= 0)
                acc = fmaf(g_zxbcdt[(size_t)(b * SEQLEN + lk) * D_IN_PROJ + D_INNER + c], wv[k], acc);
        }
        const float sv = acc / (1.f + expf(-acc));
        if (c < D_INNER)
            g_xh[(size_t)row * D_INNER + c] = sv;
        else if (c < D_INNER + D_STATE)
            g_Bm[row * D_STATE + (c - D_INNER)] = sv;
        else
            g_Cm[row * D_STATE + (c - D_INNER - D_STATE)] = sv;
    }
    if (threadIdx.x < NHEADS) {
        const int h = threadIdx.x;
        const float v = g_zxbcdt[(size_t)row * D_IN_PROJ + D_INNER + CONV_DIM + h] + dt_bias[h];
        g_dt[row * NHEADS + h] = (v > 20.f) ? v : log1pf(expf(v));
    }
}

// ---------------- sequential SSM scan ----------------
__global__ __launch_bounds__(256)
void scan_kernel(const float* __restrict__ A_log, float* __restrict__ yscan) {
    const int b  = blockIdx.x >> 5;
    const int h  = blockIdx.x & 31;
    const int t  = threadIdx.x;
    const int p  = t >> 2;
    const int nq = t & 3;
    const float Acoef = -expf(A_log[h]);

    const float* Bp = g_Bm + (size_t)b * SEQLEN * D_STATE + nq * 16;
    const float* Cp = g_Cm + (size_t)b * SEQLEN * D_STATE + nq * 16;
    const float* xp = g_xh + (size_t)b * SEQLEN * D_INNER + h * HEADDIM + p;
    const float* dp = g_dt + (size_t)b * SEQLEN * NHEADS + h;
    float*       yp = yscan + (size_t)b * SEQLEN * D_INNER + h * HEADDIM + p;

    float hs[16];
#pragma unroll
    for (int i = 0; i < 16; i++) hs[i] = 0.f;

    float B0[16], C0[16], B1[16], C1[16];
    float dt0, x0, dt1, x1;

#define LOADSTEP(BUF_B, BUF_C, BUF_DT, BUF_X, S)                               \
    do {                                                                       \
        const float* _bb = Bp + (size_t)(S) * D_STATE;                         \
        const float* _cc = Cp + (size_t)(S) * D_STATE;                         \
        *(float4*)&(BUF_B)[0]  = *(const float4*)(_bb + 0);                    \
        *(float4*)&(BUF_B)[4]  = *(const float4*)(_bb + 4);                    \
        *(float4*)&(BUF_B)[8]  = *(const float4*)(_bb + 8);                    \
        *(float4*)&(BUF_B)[12] = *(const float4*)(_bb + 12);                   \
        *(float4*)&(BUF_C)[0]  = *(const float4*)(_cc + 0);                    \
        *(float4*)&(BUF_C)[4]  = *(const float4*)(_cc + 4);                    \
        *(float4*)&(BUF_C)[8]  = *(const float4*)(_cc + 8);                    \
        *(float4*)&(BUF_C)[12] = *(const float4*)(_cc + 12);                   \
        (BUF_DT) = dp[(size_t)(S) * NHEADS];                                   \
        (BUF_X)  = xp[(size_t)(S) * D_INNER];                                  \
    } while (0)

#define COMPSTEP(BUF_B, BUF_C, BUF_DT, BUF_X, S)                               \
    do {                                                                       \
        const float dA  = expf((BUF_DT) * Acoef);                              \
        const float dtx = (BUF_DT) * (BUF_X);                                  \
        float acc = 0.f;                                                       \
        _Pragma("unroll")                                                      \
        for (int i = 0; i < 16; i++) {                                         \
            hs[i] = fmaf(hs[i], dA, dtx * (BUF_B)[i]);                         \
            acc   = fmaf(hs[i], (BUF_C)[i], acc);                              \
        }                                                                      \
        acc += __shfl_xor_sync(0xffffffffu, acc, 1);                           \
        acc += __shfl_xor_sync(0xffffffffu, acc, 2);                           \
        if (nq == 0) yp[(size_t)(S) * D_INNER] = acc;                          \
    } while (0)

    LOADSTEP(B0, C0, dt0, x0, 0);
    for (int s = 0; s < SEQLEN; s += 2) {
        LOADSTEP(B1, C1, dt1, x1, s + 1);
        COMPSTEP(B0, C0, dt0, x0, s);
        if (s + 2 < SEQLEN) LOADSTEP(B0, C0, dt0, x0, s + 2);
        COMPSTEP(B1, C1, dt1, x1, s + 1);
    }
#undef LOADSTEP
#undef COMPSTEP
}

// ---------------- gate + RMSNorm (emits tf32-rounded y) ----------------
__global__ __launch_bounds__(256)
void gate_norm_kernel(const float* __restrict__ Dv, const float* __restrict__ norm_w) {
    const int row = blockIdx.x;
    const size_t base = (size_t)row * D_INNER;

    float vals[8];
    float ss = 0.f;
#pragma unroll
    for (int i = 0; i < 8; i++) {
        const int c = threadIdx.x + i * 256;
        const float yv = g_yscan[base + c] + g_xh[base + c] * Dv[c >> 6];
        const float z  = g_zxbcdt[(size_t)row * D_IN_PROJ + c];
        const float y  = yv * (z / (1.f + expf(-z)));
        vals[i] = y;
        ss = fmaf(y, y, ss);
    }
#pragma unroll
    for (int o = 16; o > 0; o >>= 1) ss += __shfl_xor_sync(0xffffffffu, ss, o);
    __shared__ float wsum[8];
    if ((threadIdx.x & 31) == 0) wsum[threadIdx.x >> 5] = ss;
    __syncthreads();
    float tot = 0.f;
#pragma unroll
    for (int w = 0; w < 8; w++) tot += wsum[w];
    const float inv = rsqrtf(tot * (1.f / D_INNER) + 1e-5f);
#pragma unroll
    for (int i = 0; i < 8; i++) {
        const int c = threadIdx.x + i * 256;
        g_y[base + c] = to_tf32(vals[i] * inv * norm_w[c]);
    }
}

// ---------------- launch ----------------
extern "C" void kernel_launch(void* const* d_in, const int* in_sizes, int n_in,
                              void* d_out, int out_size) {
    (void)in_sizes; (void)n_in; (void)out_size;
    const float* x       = (const float*)d_in[0];
    const float* W_in    = (const float*)d_in[1];
    const float* conv_w  = (const float*)d_in[2];
    const float* conv_b  = (const float*)d_in[3];
    const float* dt_bias = (const float*)d_in[4];
    const float* A_log   = (const float*)d_in[5];
    const float* Dv      = (const float*)d_in[6];
    const float* norm_w  = (const float*)d_in[7];
    const float* W_out   = (const float*)d_in[8];
    float* out = (float*)d_out;

    float *zx, *ys, *yv, *xr, *w1r, *w2r;
    cudaGetSymbolAddress((void**)&zx,  g_zxbcdt);
    cudaGetSymbolAddress((void**)&ys,  g_yscan);
    cudaGetSymbolAddress((void**)&yv,  g_y);
    cudaGetSymbolAddress((void**)&xr,  g_xr);
    cudaGetSymbolAddress((void**)&w1r, g_w1r);
    cudaGetSymbolAddress((void**)&w2r, g_w2r);

    cudaFuncSetAttribute(gemm_tf32_pipe, cudaFuncAttributeMaxDynamicSharedMemorySize, GEMM_SMEM);

    // 0) round operands to tf32-in-fp32 (exact cp.async copies later)
    {
        const size_t nx = (size_t)NROWS * D_MODEL / 4;
        round_tf32_kernel<<<(unsigned)((nx + 255) / 256), 256>>>(x, xr, nx);
        const size_t n1 = (size_t)D_MODEL * D_IN_PROJ / 4;
        round_tf32_kernel<<<(unsigned)((n1 + 255) / 256), 256>>>(W_in, w1r, n1);
        const size_t n2 = (size_t)D_INNER * D_MODEL / 4;
        round_tf32_kernel<<<(unsigned)((n2 + 255) / 256), 256>>>(W_out, w2r, n2);
    }

    // 1) zxbcdt = x @ W_in   [8192 x 4256], K=1024
    {
        dim3 g((D_IN_PROJ + 127) / 128, NROWS / 128);
        gemm_tf32_pipe<<<g, 256, GEMM_SMEM>>>(xr, w1r, zx, NROWS, D_IN_PROJ, D_MODEL);
    }

    // 2) conv + silu + dt softplus
    conv_dt_kernel<<<NROWS, 256>>>(conv_w, conv_b, dt_bias);

    // 3) SSM scan
    scan_kernel<<<BATCH * NHEADS, 256>>>(A_log, ys);

    // 4) gate + RMSNorm (emits tf32-rounded y)
    gate_norm_kernel<<<NROWS, 256>>>(Dv, norm_w);

    // 5) out = y @ W_out   [8192 x 1024], K=2048
    {
        dim3 g(D_MODEL / 128, NROWS / 128);
        gemm_tf32_pipe<<<g, 256, GEMM_SMEM>>>(yv, w2r, out, NROWS, D_MODEL, D_INNER);
    }
}